// round 10
// baseline (speedup 1.0000x reference)
#include <cuda_runtime.h>
#include <cstdint>

#define T_LEN   1048576
#define KSTEPS  512
#define NSLOTS  4
#define NCHUNK  (T_LEN / KSTEPS)

// shared memory layout (bytes)
#define OFF_PF   0                         // p_full[4]   (8B each)
#define OFF_PC   32                        // p_cons[4]
#define OFF_WF   64                        // w_full[4]
#define OFF_WE   96                        // w_free[4]
#define OFF_P    256                       // p ring: 4 slots x 512 steps x 64B
#define PSLOT    (KSTEPS * 64)
#define OFF_W    (OFF_P + NSLOTS * PSLOT)  // w ring: 4 slots x 512 steps x 32B
#define WSLOT    (KSTEPS * 32)
#define SMEM_SZ  (OFF_W + NSLOTS * WSLOT + 256)  // pad for prefetch overrun

typedef unsigned long long ull;
typedef unsigned int u32;

__device__ __forceinline__ void mbar_init(u32 a, u32 cnt) {
    asm volatile("mbarrier.init.shared.b64 [%0], %1;" :: "r"(a), "r"(cnt) : "memory");
}
__device__ __forceinline__ void mbar_arrive(u32 a) {
    asm volatile("mbarrier.arrive.release.cta.shared::cta.b64 _, [%0];" :: "r"(a) : "memory");
}
__device__ __forceinline__ void mbar_wait(u32 a, u32 par) {
    u32 done;
    asm volatile(
        "{\n\t.reg .pred p;\n\t"
        "mbarrier.try_wait.parity.acquire.cta.shared::cta.b64 p, [%1], %2;\n\t"
        "selp.b32 %0, 1, 0, p;\n\t}"
        : "=r"(done) : "r"(a), "r"(par) : "memory");
    if (!done) {
        asm volatile(
            "{\n\t.reg .pred P1;\n\t"
            "WL_%=:\n\t"
            "mbarrier.try_wait.parity.acquire.cta.shared::cta.b64 P1, [%0], %1, 0x989680;\n\t"
            "@P1 bra.uni WD_%=;\n\t"
            "bra.uni WL_%=;\n\t"
            "WD_%=:\n\t}"
            :: "r"(a), "r"(par) : "memory");
    }
}

// packed add: two bit-exact IEEE-rn f32 adds, one instruction, TWO operands
// (vs FFMA2's three) -> register-bank rt 2 instead of 3.
__device__ __forceinline__ ull add2(ull a, ull c) {
    ull r; asm("add.rn.f32x2 %0, %1, %2;" : "=l"(r) : "l"(a), "l"(c));
    return r;
}
// pack/unpack in C++: resolved by register allocation, not real MOVs.
__device__ __forceinline__ ull fpack2(float lo, float hi) {
    union { float f[2]; ull u; } v; v.f[0] = lo; v.f[1] = hi; return v.u;
}
__device__ __forceinline__ float flo(ull x) {
    union { ull u; float f[2]; } v; v.u = x; return v.f[0];
}
__device__ __forceinline__ float fhi(ull x) {
    union { ull u; float f[2]; } v; v.u = x; return v.f[1];
}

__global__ void __launch_bounds__(352, 1)
va_main(const float* __restrict__ y, const float* __restrict__ sp, float* __restrict__ out)
{
    extern __shared__ char smem[];
    u32 sb = (u32)__cvta_generic_to_shared(smem);
    int tid = threadIdx.x, wid = tid >> 5, lane = tid & 31;

    if (tid == 0) {
        for (int s = 0; s < NSLOTS; s++) {
            mbar_init(sb + OFF_PF + 8 * s, 64); // 64 fetch lanes arrive
            mbar_init(sb + OFF_PC + 8 * s, 1);  // producer arrives
            mbar_init(sb + OFF_WF + 8 * s, 1);  // producer arrives
            mbar_init(sb + OFF_WE + 8 * s, 8);  // 8 bit-warp leaders arrive
        }
    }
    __syncthreads();

    if (wid == 10) {
        // -------- serial Viterbi producer (highest wid wins arbitration).
        // Split-pair layout: E0=(w0,w2) O0=(w1,w3) E1=(w4,w6) O1=(w5,w7).
        // 8 packed ADD2 (2-operand: bank rt 2) do all 16 adds; 8 scalar FMNMX
        // read pair components directly. Distance-1 prefetch keeps live regs
        // under the 64-reg allocation (no spills). Unroll 8 (proven shape). --
        if (lane == 0) {
            ull E0 = 0ull, O0 = 0ull, E1 = 0ull, O1 = 0ull;
            for (int c = 0; c < NCHUNK; c++) {
                int s = c & 3;
                mbar_wait(sb + OFF_PF + 8 * s, (c >> 2) & 1);
                if (c >= NSLOTS) mbar_wait(sb + OFF_WE + 8 * s, ((c - NSLOTS) >> 2) & 1);
                const ulonglong2* __restrict__ pp =
                    (const ulonglong2*)(smem + OFF_P + s * PSLOT);   // 4 per step
                float4* __restrict__ wp =
                    (float4*)(smem + OFF_W + s * WSLOT);             // 2 per step
                // distance-1 prefetch (ring has pad; overrun values unused)
                ulonglong2 a0 = pp[0], a1 = pp[1], a2 = pp[2], a3 = pp[3];
                #pragma unroll 8
                for (int k = 0; k < KSTEPS; k++) {
                    ulonglong2 n0 = pp[4 * k + 4];
                    // a_.x = even pair (p_e0,p_e1), a_.y = odd pair (helper layout)
                    ull mEa = add2(E0, a0.x);   // (m0,  m2)
                    ull mOa = add2(O0, a0.y);   // (m1,  m3)
                    ulonglong2 n1 = pp[4 * k + 5];
                    ull mEb = add2(E1, a1.x);   // (m4,  m6)
                    ull mOb = add2(O1, a1.y);   // (m5,  m7)
                    ulonglong2 n2 = pp[4 * k + 6];
                    ull mEc = add2(E0, a2.x);   // (m8,  m10)
                    ull mOc = add2(O0, a2.y);   // (m9,  m11)
                    ulonglong2 n3 = pp[4 * k + 7];
                    ull mEd = add2(E1, a3.x);   // (m12, m14)
                    ull mOd = add2(O1, a3.y);   // (m13, m15)
                    // o[q] = min(m[2q], m[2q+1]) -- scalar mins on components
                    float o0 = fminf(flo(mEa), flo(mOa));
                    float o1 = fminf(fhi(mEa), fhi(mOa));
                    float o2 = fminf(flo(mEb), flo(mOb));
                    float o3 = fminf(fhi(mEb), fhi(mOb));
                    float o4 = fminf(flo(mEc), flo(mOc));
                    float o5 = fminf(fhi(mEc), fhi(mOc));
                    float o6 = fminf(flo(mEd), flo(mOd));
                    float o7 = fminf(fhi(mEd), fhi(mOd));
                    // export in split order (bit warps un-permute for free)
                    wp[2 * k + 0] = make_float4(o0, o2, o1, o3);
                    wp[2 * k + 1] = make_float4(o4, o6, o5, o7);
                    E0 = fpack2(o0, o2); O0 = fpack2(o1, o3);
                    E1 = fpack2(o4, o6); O1 = fpack2(o5, o7);
                    a0 = n0; a1 = n1; a2 = n2; a3 = n3;
                }
                mbar_arrive(sb + OFF_PC + 8 * s);
                mbar_arrive(sb + OFF_WF + 8 * s);
            }
        }
    } else if (wid < 2) {
        // -------- branch-metric producers: p[t][u] = |y[t] - sp[u]|,
        // written in split-pair order (4q, 4q+2, 4q+1, 4q+3) --------
        int base = wid * 32 + lane;         // 0..63
        int quad = base & 3;                // fixed 4-state group per lane
        float s0 = sp[quad * 4 + 0], s1 = sp[quad * 4 + 2];
        float s2 = sp[quad * 4 + 1], s3 = sp[quad * 4 + 3];
        for (int c = 0; c < NCHUNK; c++) {
            int s = c & 3;
            if (c >= NSLOTS) mbar_wait(sb + OFF_PC + 8 * s, ((c - NSLOTS) >> 2) & 1);
            float4* __restrict__ pb = (float4*)(smem + OFF_P + s * PSLOT);
            const float* yc = y + c * KSTEPS;
            #pragma unroll 4
            for (int it = 0; it < 32; it++) {
                int idx = it * 64 + base;
                int k = idx >> 2;           // step within chunk
                float yv = __ldg(&yc[k]);
                pb[k * 4 + quad] = make_float4(fabsf(yv - s0), fabsf(yv - s1),
                                               fabsf(yv - s2), fabsf(yv - s3));
            }
            mbar_arrive(sb + OFF_PF + 8 * s);
        }
    } else {
        // -------- bit extractors: bit[t] = argmin(w_t) % 2.
        // W stored split-pair: mem = (o0,o2,o1,o3, o4,o6,o5,o7); scan in
        // LOGICAL index order o0..o7 (strict < = first-index ties, matching
        // jnp.argmin over the duplicated 16-vector). --------
        int btid = tid - 64;                // 0..255 (wid 2..9)
        if (btid == 0) out[0] = 0.0f;       // v_0 = zeros -> argmin = 0 -> bit 0
        const float4* wr = (const float4*)(smem + OFF_W);
        for (int c = 0; c < NCHUNK; c++) {
            int s = c & 3;
            mbar_wait(sb + OFF_WF + 8 * s, (c >> 2) & 1);
            #pragma unroll
            for (int r = 0; r < 2; r++) {
                int k = r * 256 + btid;
                int i = c * KSTEPS + k;     // producer step index; W[i] = w_{i+1}
                if (i != T_LEN - 1) {
                    const float4* p = wr + (size_t)(s * KSTEPS + k) * 2;
                    float4 a = p[0], b = p[1];
                    // logical order: o0=a.x o1=a.z o2=a.y o3=a.w
                    //                o4=b.x o5=b.z o6=b.y o7=b.w
                    float best = a.x; int bi = 0;            // o0
                    if (a.z < best) { best = a.z; bi = 1; }  // o1
                    if (a.y < best) { best = a.y; bi = 2; }  // o2
                    if (a.w < best) { best = a.w; bi = 3; }  // o3
                    if (b.x < best) { best = b.x; bi = 4; }  // o4
                    if (b.z < best) { best = b.z; bi = 5; }  // o5
                    if (b.y < best) { best = b.y; bi = 6; }  // o6
                    if (b.w < best) {            bi = 7; }   // o7
                    out[i + 1] = (float)(bi & 1);
                }
            }
            __syncwarp();
            if (lane == 0) mbar_arrive(sb + OFF_WE + 8 * s);
        }
    }
}

extern "C" void kernel_launch(void* const* d_in, const int* in_sizes, int n_in,
                              void* d_out, int out_size)
{
    const float* a = (const float*)d_in[0];
    const float* b = (const float*)d_in[1];
    const float* y;
    const float* sp;
    if (in_sizes[0] == 16) { sp = a; y = b; }
    else                   { y = a;  sp = b; }

    cudaFuncSetAttribute(va_main, cudaFuncAttributeMaxDynamicSharedMemorySize, SMEM_SZ);
    va_main<<<1, 352, SMEM_SZ>>>(y, sp, (float*)d_out);
}

// round 11
// speedup vs baseline: 1.1729x; 1.1729x over previous
#include <cuda_runtime.h>
#include <cstdint>

#define T_LEN   1048576
#define KSTEPS  512
#define NSLOTS  4
#define NCHUNK  (T_LEN / KSTEPS)

// shared memory layout (bytes)
#define OFF_PF   0                         // p_full[4]   (8B each)
#define OFF_PC   32                        // p_cons[4]
#define OFF_WF   64                        // w_full[4]
#define OFF_WE   96                        // w_free[4]
#define OFF_P    256                       // p ring: 4 slots x 512 steps x 64B
#define PSLOT    (KSTEPS * 64)
#define OFF_W    (OFF_P + NSLOTS * PSLOT)  // w ring: 4 slots x 512 steps x 32B
#define WSLOT    (KSTEPS * 32)
#define SMEM_SZ  (OFF_W + NSLOTS * WSLOT + 256)  // pad for prefetch overrun

typedef unsigned long long ull;
typedef unsigned int u32;

__device__ __forceinline__ void mbar_init(u32 a, u32 cnt) {
    asm volatile("mbarrier.init.shared.b64 [%0], %1;" :: "r"(a), "r"(cnt) : "memory");
}
__device__ __forceinline__ void mbar_arrive(u32 a) {
    asm volatile("mbarrier.arrive.release.cta.shared::cta.b64 _, [%0];" :: "r"(a) : "memory");
}
__device__ __forceinline__ void mbar_wait(u32 a, u32 par) {
    u32 done;
    asm volatile(
        "{\n\t.reg .pred p;\n\t"
        "mbarrier.try_wait.parity.acquire.cta.shared::cta.b64 p, [%1], %2;\n\t"
        "selp.b32 %0, 1, 0, p;\n\t}"
        : "=r"(done) : "r"(a), "r"(par) : "memory");
    if (!done) {
        asm volatile(
            "{\n\t.reg .pred P1;\n\t"
            "WL_%=:\n\t"
            "mbarrier.try_wait.parity.acquire.cta.shared::cta.b64 P1, [%0], %1, 0x989680;\n\t"
            "@P1 bra.uni WD_%=;\n\t"
            "bra.uni WL_%=;\n\t"
            "WD_%=:\n\t}"
            :: "r"(a), "r"(par) : "memory");
    }
}

// packed add: two bit-exact IEEE-rn f32 adds, one instruction, TWO source
// operand pairs (vs FFMA2's three) -> RF-bank rt 2 instead of 3.
__device__ __forceinline__ ull add2(ull a, ull c) {
    ull r; asm("add.rn.f32x2 %0, %1, %2;" : "=l"(r) : "l"(a), "l"(c));
    return r;
}
// pack/unpack in C++: resolved by register allocation, not real MOVs.
__device__ __forceinline__ ull fpack2(float lo, float hi) {
    union { float f[2]; ull u; } v; v.f[0] = lo; v.f[1] = hi; return v.u;
}
__device__ __forceinline__ float flo(ull x) {
    union { ull u; float f[2]; } v; v.u = x; return v.f[0];
}
__device__ __forceinline__ float fhi(ull x) {
    union { ull u; float f[2]; } v; v.u = x; return v.f[1];
}

__global__ void __launch_bounds__(352, 1)
va_main(const float* __restrict__ y, const float* __restrict__ sp, float* __restrict__ out)
{
    extern __shared__ char smem[];
    u32 sb = (u32)__cvta_generic_to_shared(smem);
    int tid = threadIdx.x, wid = tid >> 5, lane = tid & 31;

    if (tid == 0) {
        for (int s = 0; s < NSLOTS; s++) {
            mbar_init(sb + OFF_PF + 8 * s, 64); // 64 fetch lanes arrive
            mbar_init(sb + OFF_PC + 8 * s, 1);  // producer arrives
            mbar_init(sb + OFF_WF + 8 * s, 1);  // producer arrives
            mbar_init(sb + OFF_WE + 8 * s, 8);  // 8 bit-warp leaders arrive
        }
    }
    __syncthreads();

    if (wid == 10) {
        // -------- serial Viterbi producer (highest wid wins arbitration).
        // Split-pair layout: E0=(w0,w2) O0=(w1,w3) E1=(w4,w6) O1=(w5,w7).
        // 8 packed ADD2 do all 16 adds; 8 scalar FMNMX read pair components
        // directly (no unpack); export order == pair layout (no repack).
        // Distance-2 prefetch: loads issue ~2 steps ahead of consumption. ----
        if (lane == 0) {
            ull E0 = 0ull, O0 = 0ull, E1 = 0ull, O1 = 0ull;
            for (int c = 0; c < NCHUNK; c++) {
                int s = c & 3;
                mbar_wait(sb + OFF_PF + 8 * s, (c >> 2) & 1);
                if (c >= NSLOTS) mbar_wait(sb + OFF_WE + 8 * s, ((c - NSLOTS) >> 2) & 1);
                const ulonglong2* __restrict__ pp =
                    (const ulonglong2*)(smem + OFF_P + s * PSLOT);   // 4 per step
                float4* __restrict__ wp =
                    (float4*)(smem + OFF_W + s * WSLOT);             // 2 per step
                // distance-2 prefetch (ring has +256B pad for the overrun)
                ulonglong2 a0 = pp[0], a1 = pp[1], a2 = pp[2], a3 = pp[3];
                ulonglong2 b0 = pp[4], b1 = pp[5], b2 = pp[6], b3 = pp[7];
                #pragma unroll 16
                for (int k = 0; k < KSTEPS; k++) {
                    ulonglong2 c0 = pp[4 * k +  8];
                    // a_.x = even pair (p_e0,p_e1), a_.y = odd pair (helper layout)
                    ull mEa = add2(E0, a0.x);   // (m0,  m2)
                    ull mOa = add2(O0, a0.y);   // (m1,  m3)
                    ulonglong2 c1 = pp[4 * k +  9];
                    ull mEb = add2(E1, a1.x);   // (m4,  m6)
                    ull mOb = add2(O1, a1.y);   // (m5,  m7)
                    ulonglong2 c2 = pp[4 * k + 10];
                    ull mEc = add2(E0, a2.x);   // (m8,  m10)
                    ull mOc = add2(O0, a2.y);   // (m9,  m11)
                    ulonglong2 c3 = pp[4 * k + 11];
                    ull mEd = add2(E1, a3.x);   // (m12, m14)
                    ull mOd = add2(O1, a3.y);   // (m13, m15)
                    // o[q] = min(m[2q], m[2q+1]) -- scalar mins on components
                    float o0 = fminf(flo(mEa), flo(mOa));
                    float o1 = fminf(fhi(mEa), fhi(mOa));
                    float o2 = fminf(flo(mEb), flo(mOb));
                    float o3 = fminf(fhi(mEb), fhi(mOb));
                    float o4 = fminf(flo(mEc), flo(mOc));
                    float o5 = fminf(fhi(mEc), fhi(mOc));
                    float o6 = fminf(flo(mEd), flo(mOd));
                    float o7 = fminf(fhi(mEd), fhi(mOd));
                    // export in split order (bit warps un-permute for free)
                    wp[2 * k + 0] = make_float4(o0, o2, o1, o3);
                    wp[2 * k + 1] = make_float4(o4, o6, o5, o7);
                    E0 = fpack2(o0, o2); O0 = fpack2(o1, o3);
                    E1 = fpack2(o4, o6); O1 = fpack2(o5, o7);
                    a0 = b0; a1 = b1; a2 = b2; a3 = b3;
                    b0 = c0; b1 = c1; b2 = c2; b3 = c3;
                }
                mbar_arrive(sb + OFF_PC + 8 * s);
                mbar_arrive(sb + OFF_WF + 8 * s);
            }
        }
    } else if (wid < 2) {
        // -------- branch-metric producers: p[t][u] = |y[t] - sp[u]|,
        // written in split-pair order (4q, 4q+2, 4q+1, 4q+3) --------
        int base = wid * 32 + lane;         // 0..63
        int quad = base & 3;                // fixed 4-state group per lane
        float s0 = sp[quad * 4 + 0], s1 = sp[quad * 4 + 2];
        float s2 = sp[quad * 4 + 1], s3 = sp[quad * 4 + 3];
        for (int c = 0; c < NCHUNK; c++) {
            int s = c & 3;
            if (c >= NSLOTS) mbar_wait(sb + OFF_PC + 8 * s, ((c - NSLOTS) >> 2) & 1);
            float4* __restrict__ pb = (float4*)(smem + OFF_P + s * PSLOT);
            const float* yc = y + c * KSTEPS;
            #pragma unroll 4
            for (int it = 0; it < 32; it++) {
                int idx = it * 64 + base;
                int k = idx >> 2;           // step within chunk
                float yv = __ldg(&yc[k]);
                pb[k * 4 + quad] = make_float4(fabsf(yv - s0), fabsf(yv - s1),
                                               fabsf(yv - s2), fabsf(yv - s3));
            }
            mbar_arrive(sb + OFF_PF + 8 * s);
        }
    } else {
        // -------- bit extractors: bit[t] = argmin(w_t) % 2.
        // W stored split-pair: mem = (o0,o2,o1,o3, o4,o6,o5,o7); scan in
        // LOGICAL index order o0..o7 (strict < = first-index ties, matching
        // jnp.argmin over the duplicated 16-vector). --------
        int btid = tid - 64;                // 0..255 (wid 2..9)
        if (btid == 0) out[0] = 0.0f;       // v_0 = zeros -> argmin = 0 -> bit 0
        const float4* wr = (const float4*)(smem + OFF_W);
        for (int c = 0; c < NCHUNK; c++) {
            int s = c & 3;
            mbar_wait(sb + OFF_WF + 8 * s, (c >> 2) & 1);
            #pragma unroll
            for (int r = 0; r < 2; r++) {
                int k = r * 256 + btid;
                int i = c * KSTEPS + k;     // producer step index; W[i] = w_{i+1}
                if (i != T_LEN - 1) {
                    const float4* p = wr + (size_t)(s * KSTEPS + k) * 2;
                    float4 a = p[0], b = p[1];
                    // logical order: o0=a.x o1=a.z o2=a.y o3=a.w
                    //                o4=b.x o5=b.z o6=b.y o7=b.w
                    float best = a.x; int bi = 0;            // o0
                    if (a.z < best) { best = a.z; bi = 1; }  // o1
                    if (a.y < best) { best = a.y; bi = 2; }  // o2
                    if (a.w < best) { best = a.w; bi = 3; }  // o3
                    if (b.x < best) { best = b.x; bi = 4; }  // o4
                    if (b.z < best) { best = b.z; bi = 5; }  // o5
                    if (b.y < best) { best = b.y; bi = 6; }  // o6
                    if (b.w < best) {            bi = 7; }   // o7
                    out[i + 1] = (float)(bi & 1);
                }
            }
            __syncwarp();
            if (lane == 0) mbar_arrive(sb + OFF_WE + 8 * s);
        }
    }
}

extern "C" void kernel_launch(void* const* d_in, const int* in_sizes, int n_in,
                              void* d_out, int out_size)
{
    const float* a = (const float*)d_in[0];
    const float* b = (const float*)d_in[1];
    const float* y;
    const float* sp;
    if (in_sizes[0] == 16) { sp = a; y = b; }
    else                   { y = a;  sp = b; }

    cudaFuncSetAttribute(va_main, cudaFuncAttributeMaxDynamicSharedMemorySize, SMEM_SZ);
    va_main<<<1, 352, SMEM_SZ>>>(y, sp, (float*)d_out);
}

// round 12
// speedup vs baseline: 1.2473x; 1.0634x over previous
#include <cuda_runtime.h>
#include <cstdint>

#define T_LEN   1048576
#define KSTEPS  512
#define NSLOTS  4
#define NCHUNK  (T_LEN / KSTEPS)

// shared memory layout (bytes)
#define OFF_PF   0                         // p_full[4]   (8B each)
#define OFF_PC   32                        // p_cons[4]
#define OFF_WF   64                        // w_full[4]
#define OFF_WE   96                        // w_free[4]
#define OFF_P    256                       // p ring: 4 slots x 512 steps x 64B
#define PSLOT    (KSTEPS * 64)
#define OFF_W    (OFF_P + NSLOTS * PSLOT)  // w ring: 4 slots x 512 steps x 32B
#define WSLOT    (KSTEPS * 32)
#define SMEM_SZ  (OFF_W + NSLOTS * WSLOT + 256)  // pad for prefetch overrun

typedef unsigned long long ull;
typedef unsigned int u32;

__device__ __forceinline__ void mbar_init(u32 a, u32 cnt) {
    asm volatile("mbarrier.init.shared.b64 [%0], %1;" :: "r"(a), "r"(cnt) : "memory");
}
__device__ __forceinline__ void mbar_arrive(u32 a) {
    asm volatile("mbarrier.arrive.release.cta.shared::cta.b64 _, [%0];" :: "r"(a) : "memory");
}
__device__ __forceinline__ void mbar_wait(u32 a, u32 par) {
    u32 done;
    asm volatile(
        "{\n\t.reg .pred p;\n\t"
        "mbarrier.try_wait.parity.acquire.cta.shared::cta.b64 p, [%1], %2;\n\t"
        "selp.b32 %0, 1, 0, p;\n\t}"
        : "=r"(done) : "r"(a), "r"(par) : "memory");
    if (!done) {
        asm volatile(
            "{\n\t.reg .pred P1;\n\t"
            "WL_%=:\n\t"
            "mbarrier.try_wait.parity.acquire.cta.shared::cta.b64 P1, [%0], %1, 0x989680;\n\t"
            "@P1 bra.uni WD_%=;\n\t"
            "bra.uni WL_%=;\n\t"
            "WD_%=:\n\t}"
            :: "r"(a), "r"(par) : "memory");
    }
}

// packed add: two bit-exact IEEE-rn f32 adds in one instruction.
__device__ __forceinline__ ull add2(ull a, ull c) {
    ull r; asm("add.rn.f32x2 %0, %1, %2;" : "=l"(r) : "l"(a), "l"(c));
    return r;
}
// pack/unpack in C++: resolved by register allocation, not real MOVs.
__device__ __forceinline__ ull fpack2(float lo, float hi) {
    union { float f[2]; ull u; } v; v.f[0] = lo; v.f[1] = hi; return v.u;
}
__device__ __forceinline__ float flo(ull x) {
    union { ull u; float f[2]; } v; v.u = x; return v.f[0];
}
__device__ __forceinline__ float fhi(ull x) {
    union { ull u; float f[2]; } v; v.u = x; return v.f[1];
}

__global__ void __launch_bounds__(448, 1)
va_main(const float* __restrict__ y, const float* __restrict__ sp, float* __restrict__ out)
{
    extern __shared__ char smem[];
    u32 sb = (u32)__cvta_generic_to_shared(smem);
    int tid = threadIdx.x, wid = tid >> 5, lane = tid & 31;

    if (tid == 0) {
        for (int s = 0; s < NSLOTS; s++) {
            mbar_init(sb + OFF_PF + 8 * s, 64); // 64 fetch lanes arrive
            mbar_init(sb + OFF_PC + 8 * s, 1);  // producer arrives
            mbar_init(sb + OFF_WF + 8 * s, 1);  // producer arrives
            mbar_init(sb + OFF_WE + 8 * s, 8);  // 8 bit-warp leaders arrive
        }
    }
    __syncthreads();

    // Warp->SMSP map is wid%4. Producer owns SMSP3 EXCLUSIVELY: it is wid 11,
    // and the other SMSP3 warps (3, 7) plus spare warp 13 exit immediately —
    // retired warps don't arbitrate, so no HOLD-retention theft of the
    // producer's issue slots is possible.
    if (wid == 3 || wid == 7 || wid == 13) return;

    if (wid == 11) {
        // -------- serial Viterbi producer, private SMSP --------
        // Split-pair layout: E0=(w0,w2) O0=(w1,w3) E1=(w4,w6) O1=(w5,w7).
        // 8 packed ADD2 do all 16 adds; 8 scalar FMNMX read pair components.
        // Distance-2 prefetch: loads issue ~2 steps ahead of consumption.
        if (lane == 0) {
            ull E0 = 0ull, O0 = 0ull, E1 = 0ull, O1 = 0ull;
            for (int c = 0; c < NCHUNK; c++) {
                int s = c & 3;
                mbar_wait(sb + OFF_PF + 8 * s, (c >> 2) & 1);
                if (c >= NSLOTS) mbar_wait(sb + OFF_WE + 8 * s, ((c - NSLOTS) >> 2) & 1);
                const ulonglong2* __restrict__ pp =
                    (const ulonglong2*)(smem + OFF_P + s * PSLOT);   // 4 per step
                float4* __restrict__ wp =
                    (float4*)(smem + OFF_W + s * WSLOT);             // 2 per step
                // distance-2 prefetch (ring has +256B pad for the overrun)
                ulonglong2 a0 = pp[0], a1 = pp[1], a2 = pp[2], a3 = pp[3];
                ulonglong2 b0 = pp[4], b1 = pp[5], b2 = pp[6], b3 = pp[7];
                #pragma unroll 16
                for (int k = 0; k < KSTEPS; k++) {
                    ulonglong2 c0 = pp[4 * k +  8];
                    // a_.x = even pair (p_e0,p_e1), a_.y = odd pair (helper layout)
                    ull mEa = add2(E0, a0.x);   // (m0,  m2)
                    ull mOa = add2(O0, a0.y);   // (m1,  m3)
                    ulonglong2 c1 = pp[4 * k +  9];
                    ull mEb = add2(E1, a1.x);   // (m4,  m6)
                    ull mOb = add2(O1, a1.y);   // (m5,  m7)
                    ulonglong2 c2 = pp[4 * k + 10];
                    ull mEc = add2(E0, a2.x);   // (m8,  m10)
                    ull mOc = add2(O0, a2.y);   // (m9,  m11)
                    ulonglong2 c3 = pp[4 * k + 11];
                    ull mEd = add2(E1, a3.x);   // (m12, m14)
                    ull mOd = add2(O1, a3.y);   // (m13, m15)
                    // o[q] = min(m[2q], m[2q+1]) -- scalar mins on components
                    float o0 = fminf(flo(mEa), flo(mOa));
                    float o1 = fminf(fhi(mEa), fhi(mOa));
                    float o2 = fminf(flo(mEb), flo(mOb));
                    float o3 = fminf(fhi(mEb), fhi(mOb));
                    float o4 = fminf(flo(mEc), flo(mOc));
                    float o5 = fminf(fhi(mEc), fhi(mOc));
                    float o6 = fminf(flo(mEd), flo(mOd));
                    float o7 = fminf(fhi(mEd), fhi(mOd));
                    // export in split order (bit warps un-permute for free)
                    wp[2 * k + 0] = make_float4(o0, o2, o1, o3);
                    wp[2 * k + 1] = make_float4(o4, o6, o5, o7);
                    E0 = fpack2(o0, o2); O0 = fpack2(o1, o3);
                    E1 = fpack2(o4, o6); O1 = fpack2(o5, o7);
                    a0 = b0; a1 = b1; a2 = b2; a3 = b3;
                    b0 = c0; b1 = c1; b2 = c2; b3 = c3;
                }
                mbar_arrive(sb + OFF_PC + 8 * s);
                mbar_arrive(sb + OFF_WF + 8 * s);
            }
        }
    } else if (wid < 2) {
        // -------- branch-metric producers: p[t][u] = |y[t] - sp[u]|,
        // written in split-pair order (4q, 4q+2, 4q+1, 4q+3) --------
        int base = wid * 32 + lane;         // 0..63
        int quad = base & 3;                // fixed 4-state group per lane
        float s0 = sp[quad * 4 + 0], s1 = sp[quad * 4 + 2];
        float s2 = sp[quad * 4 + 1], s3 = sp[quad * 4 + 3];
        for (int c = 0; c < NCHUNK; c++) {
            int s = c & 3;
            if (c >= NSLOTS) mbar_wait(sb + OFF_PC + 8 * s, ((c - NSLOTS) >> 2) & 1);
            float4* __restrict__ pb = (float4*)(smem + OFF_P + s * PSLOT);
            const float* yc = y + c * KSTEPS;
            #pragma unroll 4
            for (int it = 0; it < 32; it++) {
                int idx = it * 64 + base;
                int k = idx >> 2;           // step within chunk
                float yv = __ldg(&yc[k]);
                pb[k * 4 + quad] = make_float4(fabsf(yv - s0), fabsf(yv - s1),
                                               fabsf(yv - s2), fabsf(yv - s3));
            }
            mbar_arrive(sb + OFF_PF + 8 * s);
        }
    } else {
        // -------- bit extractors: bit[t] = argmin(w_t) % 2. --------
        // wids {2,4,5,6,8,9,10,12} -> bit-warp index 0..7 (none on SMSP3).
        int b8 = (wid < 3) ? (wid - 2) : (wid < 7) ? (wid - 3)
                 : (wid < 11) ? (wid - 4) : (wid - 5);
        int btid = b8 * 32 + lane;          // 0..255
        if (btid == 0) out[0] = 0.0f;       // v_0 = zeros -> argmin = 0 -> bit 0
        const float4* wr = (const float4*)(smem + OFF_W);
        for (int c = 0; c < NCHUNK; c++) {
            int s = c & 3;
            mbar_wait(sb + OFF_WF + 8 * s, (c >> 2) & 1);
            #pragma unroll
            for (int r = 0; r < 2; r++) {
                int k = r * 256 + btid;
                int i = c * KSTEPS + k;     // producer step index; W[i] = w_{i+1}
                if (i != T_LEN - 1) {
                    const float4* p = wr + (size_t)(s * KSTEPS + k) * 2;
                    float4 a = p[0], b = p[1];
                    // W stored split-pair: (o0,o2,o1,o3 | o4,o6,o5,o7); scan in
                    // LOGICAL order o0..o7 (strict < = first-index ties, matching
                    // jnp.argmin over the duplicated 16-vector).
                    float best = a.x; int bi = 0;            // o0
                    if (a.z < best) { best = a.z; bi = 1; }  // o1
                    if (a.y < best) { best = a.y; bi = 2; }  // o2
                    if (a.w < best) { best = a.w; bi = 3; }  // o3
                    if (b.x < best) { best = b.x; bi = 4; }  // o4
                    if (b.z < best) { best = b.z; bi = 5; }  // o5
                    if (b.y < best) { best = b.y; bi = 6; }  // o6
                    if (b.w < best) {            bi = 7; }   // o7
                    out[i + 1] = (float)(bi & 1);
                }
            }
            __syncwarp();
            if (lane == 0) mbar_arrive(sb + OFF_WE + 8 * s);
        }
    }
}

extern "C" void kernel_launch(void* const* d_in, const int* in_sizes, int n_in,
                              void* d_out, int out_size)
{
    const float* a = (const float*)d_in[0];
    const float* b = (const float*)d_in[1];
    const float* y;
    const float* sp;
    if (in_sizes[0] == 16) { sp = a; y = b; }
    else                   { y = a;  sp = b; }

    cudaFuncSetAttribute(va_main, cudaFuncAttributeMaxDynamicSharedMemorySize, SMEM_SZ);
    va_main<<<1, 448, SMEM_SZ>>>(y, sp, (float*)d_out);
}